// round 17
// baseline (speedup 1.0000x reference)
#include <cuda_runtime.h>
#include <cuda_fp16.h>
#include <cstdint>
#include <math.h>

#define NTOK 8192
#define DDIM 512
#define FDIM 2048
#define GDIM 102
#define GAMMA_C 0.5f
#define NEG_C -1e9f
#define SCALE_C 0.044194173824159216f

typedef __half hlf;

#define BM 256
#define BN 128
#define BKE 64
#define A_BYTES (BM * 128)
#define B_BYTES (BN * 128)
#define STGB (2 * A_BYTES + 2 * B_BYTES)
#define GEMM_SMEM (2 * STGB + 1024)

struct Scratch {
    float Sr[(size_t)NTOK * NTOK];
    float Sf[(size_t)NTOK * NTOK];
    hlf attn_h[(size_t)NTOK * NTOK];
    float dropx[NTOK * DDIM];
    float attnout[NTOK * DDIM];
    float h1[NTOK * DDIM];
    float h2[NTOK * DDIM];
    float head[NTOK * DDIM];
    hlf dropx_h[NTOK * DDIM], dropx_l[NTOK * DDIM];
    hlf QKr_h[NTOK * 2 * DDIM], QKr_l[NTOK * 2 * DDIM];
    hlf QKf_h[NTOK * 2 * DDIM], QKf_l[NTOK * 2 * DDIM];
    hlf Vt_h[DDIM * NTOK], Vt_l[DDIM * NTOK];
    hlf h1_h[NTOK * DDIM], h1_l[NTOK * DDIM];
    hlf h2_h[NTOK * DDIM], h2_l[NTOK * DDIM];
    hlf rc_h[NTOK * DDIM], rc_l[NTOK * DDIM];
    hlf ff_h[NTOK * FDIM], ff_l[NTOK * FDIM];
    hlf w_h[11 * DDIM * DDIM], w_l[11 * DDIM * DDIM];
    hlf w1_h[FDIM * DDIM], w1_l[FDIM * DDIM];
    hlf w2_h[DDIM * FDIM], w2_l[DDIM * FDIM];
    unsigned rbits[(size_t)NTOK * NTOK / 32];
    unsigned fbits[(size_t)NTOK * NTOK / 32];
};
__device__ Scratch g_s;

__device__ __forceinline__ uint32_t smem_u32(const void* p) {
    uint32_t a;
    asm("{ .reg .u64 t; cvta.to.shared.u64 t, %1; cvt.u32.u64 %0, t; }" : "=r"(a) : "l"(p));
    return a;
}
__device__ __forceinline__ void cpa16(uint32_t dst, const void* src) {
    asm volatile("cp.async.cg.shared.global [%0], [%1], 16;" ::"r"(dst), "l"(src) : "memory");
}
#define CPA_COMMIT() asm volatile("cp.async.commit_group;" ::: "memory")
template <int Np> __device__ __forceinline__ void cpa_wait() {
    asm volatile("cp.async.wait_group %0;" ::"n"(Np) : "memory");
}
__device__ __forceinline__ void ldsm4(uint32_t* r, uint32_t a) {
    asm volatile("ldmatrix.sync.aligned.m8n8.x4.shared.b16 {%0,%1,%2,%3}, [%4];"
                 : "=r"(r[0]), "=r"(r[1]), "=r"(r[2]), "=r"(r[3]) : "r"(a));
}
__device__ __forceinline__ void mma16816(float* c, const uint32_t* a, const uint32_t* b) {
    asm volatile(
        "mma.sync.aligned.m16n8k16.row.col.f32.f16.f16.f32 "
        "{%0,%1,%2,%3}, {%4,%5,%6,%7}, {%8,%9}, {%0,%1,%2,%3};"
        : "+f"(c[0]), "+f"(c[1]), "+f"(c[2]), "+f"(c[3])
        : "r"(a[0]), "r"(a[1]), "r"(a[2]), "r"(a[3]), "r"(b[0]), "r"(b[1]));
}
__device__ __forceinline__ uint32_t pack_h2(hlf a, hlf b) {
    return ((uint32_t)__half_as_ushort(b) << 16) | (uint32_t)__half_as_ushort(a);
}

// C[M,N] = (Ah[+Al]) @ (Bh+Bl)^T.  ALO: include Al*Bh product.
// EPI: 0 fp32 | 1 split fp16 | 2 maskbits+scale predicated fp32 | 3 bias+gelu split | 4 bias fp32
template <int EPI, int ALO>
__global__ void __launch_bounds__(256, 1) gemm_tc(
    const hlf* __restrict__ Ah_, const hlf* __restrict__ Al_,
    const hlf* __restrict__ Bh_, const hlf* __restrict__ Bl_,
    float* __restrict__ C, hlf* __restrict__ Ch, hlf* __restrict__ Cl,
    const float* __restrict__ bias, const unsigned* __restrict__ mbits,
    int N, int K, int ldA, int ldB, int ldC, float scale) {
    extern __shared__ char dsm[];
    const int tid = threadIdx.x, wid = tid >> 5, lane = tid & 31;
    const int wm = wid >> 1, wn = wid & 1;
    const uint32_t dynb = (smem_u32(dsm) + 1023) & ~1023u;
    const int rowA = blockIdx.y * BM;
    const int colB = blockIdx.x * BN;

    const int tr = tid >> 3, tc = tid & 7;
    const hlf* pAh = Ah_ + (size_t)(rowA + tr) * ldA + tc * 8;
    const hlf* pAl = ALO ? (Al_ + (size_t)(rowA + tr) * ldA + tc * 8) : pAh;
    const hlf* pBh = Bh_ + (size_t)(colB + tr) * ldB + tc * 8;
    const hlf* pBl = Bl_ + (size_t)(colB + tr) * ldB + tc * 8;

    float acc[4][8][4];
#pragma unroll
    for (int i = 0; i < 4; i++)
#pragma unroll
        for (int j = 0; j < 8; j++)
#pragma unroll
            for (int q = 0; q < 4; q++) acc[i][j][q] = 0.0f;

    auto issue = [&](int slot, int kt) {
        const uint32_t sb = dynb + slot * STGB;
        const int k0 = kt * BKE;
        const uint32_t so = (uint32_t)tr * 128 + tc * 16;
#pragma unroll
        for (int i = 0; i < 8; i++) {
            uint32_t off = so + i * 4096;
            uint32_t sw = off ^ ((off >> 3) & 0x70);
            size_t g = (size_t)i * 32 * ldA + k0;
            cpa16(sb + sw, pAh + g);
            if (ALO) cpa16(sb + A_BYTES + sw, pAl + g);
        }
#pragma unroll
        for (int i = 0; i < 4; i++) {
            uint32_t off = so + i * 4096;
            uint32_t sw = off ^ ((off >> 3) & 0x70);
            size_t g = (size_t)i * 32 * ldB + k0;
            cpa16(sb + 2 * A_BYTES + sw, pBh + g);
            cpa16(sb + 2 * A_BYTES + B_BYTES + sw, pBl + g);
        }
        CPA_COMMIT();
    };

    const int NIT = K / BKE;
    issue(0, 0);

    const uint32_t a_row = wm * 64 + (lane & 15);
    const uint32_t a_kb = (uint32_t)((lane >> 4) << 4);
    const uint32_t b_row = wn * 64 + (lane & 7) + ((lane >> 4) << 3);
    const uint32_t b_kb = (uint32_t)((lane & 8) * 2);

    for (int kt = 0; kt < NIT; kt++) {
        const int s = kt & 1;
        cpa_wait<0>();
        __syncthreads();
        if (kt + 1 < NIT) issue(s ^ 1, kt + 1);
        const uint32_t sb = dynb + s * STGB;
#pragma unroll
        for (int k16 = 0; k16 < 4; k16++) {
            uint32_t ah[4][4], al[4][4];
#pragma unroll
            for (int mt = 0; mt < 4; mt++) {
                uint32_t off = (a_row + mt * 16) * 128 + k16 * 32 + a_kb;
                uint32_t sw = off ^ ((off >> 3) & 0x70);
                ldsm4(ah[mt], sb + sw);
                if (ALO) ldsm4(al[mt], sb + A_BYTES + sw);
            }
#pragma unroll
            for (int nj = 0; nj < 4; nj++) {
                uint32_t bh[4], bl[4];
                uint32_t off = (b_row + nj * 16) * 128 + k16 * 32 + b_kb;
                uint32_t sw = off ^ ((off >> 3) & 0x70);
                ldsm4(bh, sb + 2 * A_BYTES + sw);
                ldsm4(bl, sb + 2 * A_BYTES + B_BYTES + sw);
#pragma unroll
                for (int mt = 0; mt < 4; mt++) {
                    mma16816(acc[mt][nj * 2], ah[mt], bh);
                    mma16816(acc[mt][nj * 2], ah[mt], bl);
                    if (ALO) mma16816(acc[mt][nj * 2], al[mt], bh);
                    mma16816(acc[mt][nj * 2 + 1], ah[mt], bh + 2);
                    mma16816(acc[mt][nj * 2 + 1], ah[mt], bl + 2);
                    if (ALO) mma16816(acc[mt][nj * 2 + 1], al[mt], bh + 2);
                }
            }
        }
    }

    const int r0b = rowA + wm * 64 + (lane >> 2);
    const int cb = colB + wn * 64 + 2 * (lane & 3);
#pragma unroll
    for (int mt = 0; mt < 4; mt++) {
#pragma unroll
        for (int half = 0; half < 2; half++) {
            const int r = r0b + mt * 16 + half * 8;
#pragma unroll
            for (int nt = 0; nt < 8; nt++) {
                const int c = cb + nt * 8;
                float v0 = acc[mt][nt][half * 2 + 0];
                float v1 = acc[mt][nt][half * 2 + 1];
                if (EPI == 2) {
                    unsigned w = mbits[(size_t)r * (size_t)(N >> 5) + (c >> 5)];
                    if (!((w >> (c & 31)) & 1u)) C[(size_t)r * ldC + c] = v0 * scale;
                    if (!((w >> ((c + 1) & 31)) & 1u)) C[(size_t)r * ldC + c + 1] = v1 * scale;
                    continue;
                }
                if (EPI == 3 || EPI == 4) { v0 += bias[c]; v1 += bias[c + 1]; }
                if (EPI == 3) {
                    v0 = 0.5f * v0 * (1.0f + erff(v0 * 0.70710678118654752f));
                    v1 = 0.5f * v1 * (1.0f + erff(v1 * 0.70710678118654752f));
                }
                if (EPI == 0 || EPI == 4) {
                    *(float2*)(C + (size_t)r * ldC + c) = make_float2(v0, v1);
                } else {
                    hlf h0 = __float2half(v0), h1 = __float2half(v1);
                    hlf l0 = __float2half(v0 - __half2float(h0));
                    hlf l1 = __float2half(v1 - __half2float(h1));
                    *(uint32_t*)(Ch + (size_t)r * ldC + c) = pack_h2(h0, h1);
                    *(uint32_t*)(Cl + (size_t)r * ldC + c) = pack_h2(l0, l1);
                }
            }
        }
    }
}

// ---------------- elementwise ----------------
__global__ void prep_fused_kernel(const float* __restrict__ x, const int* __restrict__ di,
                                  float* __restrict__ dx, hlf* __restrict__ H, hlf* __restrict__ L,
                                  const float* __restrict__ W0, const float* __restrict__ W1,
                                  hlf* __restrict__ Th0, hlf* __restrict__ Tl0,
                                  hlf* __restrict__ Th1, hlf* __restrict__ Tl1) {
    __shared__ float row[DDIM];
    __shared__ float t[32][33];
    const int b = blockIdx.x, tid = threadIdx.x;
    if (b < NTOK) {
        const float* xr = x + (size_t)b * DDIM;
#pragma unroll
        for (int j = 0; j < 2; j++) row[tid + 256 * j] = xr[tid + 256 * j];
        __syncthreads();
        if (tid < GDIM) row[di[(size_t)b * GDIM + tid]] = 0.0f;
        __syncthreads();
        size_t ro = (size_t)b * DDIM;
#pragma unroll
        for (int j = 0; j < 2; j++) {
            float v = row[tid + 256 * j];
            hlf h = __float2half(v);
            dx[ro + tid + 256 * j] = v;
            H[ro + tid + 256 * j] = h;
            L[ro + tid + 256 * j] = __float2half(v - __half2float(h));
        }
    } else {
        int tb = b - NTOK;
        int z = tb >> 8, rem = tb & 255;
        int c0 = (rem & 15) * 32, r0 = (rem >> 4) * 32;
        const float* X = z ? W1 : W0;
        hlf* Th = z ? Th1 : Th0;
        hlf* Tl = z ? Tl1 : Tl0;
        int tx = tid & 31, ty = tid >> 5;
#pragma unroll
        for (int j = 0; j < 4; j++) t[ty + 8 * j][tx] = X[(size_t)(r0 + ty + 8 * j) * DDIM + c0 + tx];
        __syncthreads();
#pragma unroll
        for (int j = 0; j < 4; j++) {
            float v = t[tx][ty + 8 * j];
            hlf h = __float2half(v);
            size_t o = (size_t)(c0 + ty + 8 * j) * DDIM + r0 + tx;
            Th[o] = h;
            Tl[o] = __float2half(v - __half2float(h));
        }
    }
}
__global__ void gather_out_kernel(const float* __restrict__ x, const float* __restrict__ h,
                                  const int* __restrict__ di, float* __restrict__ out) {
    int i = blockIdx.x * blockDim.x + threadIdx.x;
    if (i >= NTOK * GDIM) return;
    int row = i / GDIM, c = di[i];
    out[i] = x[(size_t)row * DDIM + c];
    out[(size_t)NTOK * GDIM + i] = h[(size_t)row * DDIM + c];
}
__global__ void tsplit2_kernel(const float* __restrict__ X0, const float* __restrict__ X1,
                               hlf* __restrict__ Th0, hlf* __restrict__ Tl0,
                               hlf* __restrict__ Th1, hlf* __restrict__ Tl1) {
    __shared__ float t[32][33];
    const float* X = blockIdx.z ? X1 : X0;
    hlf* Th = blockIdx.z ? Th1 : Th0;
    hlf* Tl = blockIdx.z ? Tl1 : Tl0;
    int c0 = blockIdx.x * 32, r0 = blockIdx.y * 32;
    int tx = threadIdx.x, ty = threadIdx.y;
#pragma unroll
    for (int j = 0; j < 4; j++) t[ty + 8 * j][tx] = X[(size_t)(r0 + ty + 8 * j) * DDIM + c0 + tx];
    __syncthreads();
#pragma unroll
    for (int j = 0; j < 4; j++) {
        float v = t[tx][ty + 8 * j];
        hlf h = __float2half(v);
        size_t o = (size_t)(c0 + ty + 8 * j) * DDIM + r0 + tx;
        Th[o] = h;
        Tl[o] = __float2half(v - __half2float(h));
    }
}
__global__ void tsplit_kernel(const float* __restrict__ X, hlf* __restrict__ Th, hlf* __restrict__ Tl,
                              int R, int C) {
    __shared__ float t[32][33];
    int c0 = blockIdx.x * 32, r0 = blockIdx.y * 32;
    int tx = threadIdx.x, ty = threadIdx.y;
#pragma unroll
    for (int j = 0; j < 4; j++) t[ty + 8 * j][tx] = X[(size_t)(r0 + ty + 8 * j) * C + c0 + tx];
    __syncthreads();
#pragma unroll
    for (int j = 0; j < 4; j++) {
        float v = t[tx][ty + 8 * j];
        hlf h = __float2half(v);
        size_t o = (size_t)(c0 + ty + 8 * j) * R + r0 + tx;
        Th[o] = h;
        Tl[o] = __float2half(v - __half2float(h));
    }
}
__global__ void pack_bits_kernel(const int* __restrict__ m, unsigned* __restrict__ bits, size_t nwords) {
    size_t gt = (size_t)blockIdx.x * 256 + threadIdx.x;
    size_t warp = gt >> 5;
    int lane = threadIdx.x & 31;
    size_t w0 = warp * 4;
    if (w0 >= nwords) return;
    size_t base = warp * 128;
    unsigned b0 = __ballot_sync(0xFFFFFFFFu, m[base + lane] != 0);
    unsigned b1 = __ballot_sync(0xFFFFFFFFu, m[base + 32 + lane] != 0);
    unsigned b2 = __ballot_sync(0xFFFFFFFFu, m[base + 64 + lane] != 0);
    unsigned b3 = __ballot_sync(0xFFFFFFFFu, m[base + 96 + lane] != 0);
    if (lane == 0) *(uint4*)(bits + w0) = make_uint4(b0, b1, b2, b3);
}

__device__ __forceinline__ float warpSum(float v) {
#pragma unroll
    for (int o = 16; o > 0; o >>= 1) v += __shfl_xor_sync(0xFFFFFFFFu, v, o);
    return v;
}
__device__ __forceinline__ float warpMax(float v) {
#pragma unroll
    for (int o = 16; o > 0; o >>= 1) v = fmaxf(v, __shfl_xor_sync(0xFFFFFFFFu, v, o));
    return v;
}

__global__ void softmax_combine_kernel(const float* __restrict__ Sr, const float* __restrict__ Sf,
                                       const unsigned* __restrict__ rb, const unsigned* __restrict__ fb,
                                       hlf* __restrict__ Ah) {
    extern __shared__ float sm[];
    float* s_r = sm;
    float* s_f = sm + NTOK;
    __shared__ float red[16];
    const int row = blockIdx.x, tid = threadIdx.x, lane = tid & 31, wid = tid >> 5;
    const float* Rr = Sr + (size_t)row * NTOK;
    const float* Rf = Sf + (size_t)row * NTOK;
    const size_t wo = (size_t)row * (NTOK / 32);
    float m = -3.4e38f;
    for (int j = tid; j < NTOK; j += 512) {
        float a = Rr[j], b = Rf[j];
        unsigned wr = rb[wo + (j >> 5)], wf = fb[wo + (j >> 5)];
        if ((wr >> (j & 31)) & 1u) a = NEG_C;
        if ((wf >> (j & 31)) & 1u) b = NEG_C;
        s_r[j] = a; s_f[j] = b;
        m = fmaxf(m, fmaxf(a, b));
    }
    m = warpMax(m);
    if (lane == 0) red[wid] = m;
    __syncthreads();
    if (wid == 0) {
        float t = (lane < 16) ? red[lane] : -3.4e38f;
        t = warpMax(t);
        if (lane == 0) red[0] = t;
    }
    __syncthreads();
    m = red[0];
    __syncthreads();
    float sum = 0.0f;
    for (int j = tid; j < NTOK; j += 512) {
        float e = __expf(s_r[j] - m) + GAMMA_C * __expf(s_f[j] - m);
        s_r[j] = e;
        sum += e;
    }
    sum = warpSum(sum);
    if (lane == 0) red[wid] = sum;
    __syncthreads();
    if (wid == 0) {
        float t = (lane < 16) ? red[lane] : 0.0f;
        t = warpSum(t);
        if (lane == 0) red[0] = t;
    }
    __syncthreads();
    float inv = 1.0f / red[0];
    size_t ro = (size_t)row * NTOK;
    for (int j = tid; j < NTOK; j += 512)
        Ah[ro + j] = __float2half(s_r[j] * inv);
}

__global__ void add_ln_kernel(const float* __restrict__ a, const float* __restrict__ b,
                              const float* __restrict__ gamma, const float* __restrict__ beta,
                              float* __restrict__ out, hlf* __restrict__ oh, hlf* __restrict__ ol) {
    __shared__ float red[8];
    const int row = blockIdx.x, tid = threadIdx.x, lane = tid & 31, wid = tid >> 5;
    const float* ar = a + (size_t)row * DDIM;
    const float* br = b + (size_t)row * DDIM;
    float v0 = ar[tid] + br[tid];
    float v1 = ar[tid + 256] + br[tid + 256];
    float s = warpSum(v0 + v1);
    if (lane == 0) red[wid] = s;
    __syncthreads();
    if (wid == 0) {
        float t = (lane < 8) ? red[lane] : 0.0f;
        t = warpSum(t);
        if (lane == 0) red[0] = t;
    }
    __syncthreads();
    float mu = red[0] * (1.0f / DDIM);
    __syncthreads();
    float d0 = v0 - mu, d1 = v1 - mu;
    float q = warpSum(d0 * d0 + d1 * d1);
    if (lane == 0) red[wid] = q;
    __syncthreads();
    if (wid == 0) {
        float t = (lane < 8) ? red[lane] : 0.0f;
        t = warpSum(t);
        if (lane == 0) red[0] = t;
    }
    __syncthreads();
    float rstd = rsqrtf(red[0] * (1.0f / DDIM) + 1e-5f);
    size_t ro = (size_t)row * DDIM;
    float o0 = d0 * rstd * gamma[tid] + beta[tid];
    float o1 = d1 * rstd * gamma[tid + 256] + beta[tid + 256];
    if (out) { out[ro + tid] = o0; out[ro + tid + 256] = o1; }
    hlf h0 = __float2half(o0), h1b = __float2half(o1);
    oh[ro + tid] = h0;
    ol[ro + tid] = __float2half(o0 - __half2float(h0));
    oh[ro + tid + 256] = h1b;
    ol[ro + tid + 256] = __float2half(o1 - __half2float(h1b));
}

// ---------------- host ----------------
static Scratch* get_s() {
    static Scratch* p = nullptr;
    if (!p) cudaGetSymbolAddress((void**)&p, g_s);
    return p;
}
#define G_TCS(EPI, ALO, M, N, Ah, Al, Bh, Bl, C, Ch, Cl, bias, mb, K, lA, lB, lC, sc, st) \
    gemm_tc<EPI, ALO><<<dim3((N) / BN, (M) / BM), 256, GEMM_SMEM, st>>>(Ah, Al, Bh, Bl, C, Ch, Cl, bias, mb, N, K, lA, lB, lC, sc)

struct Ctx {
    cudaStream_t sA, sB;
    cudaEvent_t evStart, evPackR, evPrep, evW23, evSf, evVt, evFF, evH2,
        evW56, evW78, evW910, evSfD, evVtD;
    Ctx() {
        cudaStreamCreateWithFlags(&sA, cudaStreamNonBlocking);
        cudaStreamCreateWithFlags(&sB, cudaStreamNonBlocking);
        cudaEvent_t* evs[] = { &evStart, &evPackR, &evPrep, &evW23, &evSf, &evVt, &evFF,
                               &evH2, &evW56, &evW78, &evW910, &evSfD, &evVtD };
        for (auto e : evs) cudaEventCreateWithFlags(e, cudaEventDisableTiming);
    }
};

extern "C" void kernel_launch(void* const* d_in, const int* in_sizes, int n_in,
                              void* d_out, int out_size) {
    const float* x = (const float*)d_in[0];
    const int* drop_idx = (const int*)d_in[1];
    const int* rmask = (const int*)d_in[2];
    const int* fmask = (const int*)d_in[3];
    const float* W[11] = { (const float*)d_in[4], (const float*)d_in[5], (const float*)d_in[6],
                           (const float*)d_in[7], (const float*)d_in[8], (const float*)d_in[9],
                           (const float*)d_in[10], (const float*)d_in[11], (const float*)d_in[12],
                           (const float*)d_in[13], (const float*)d_in[24] };
    const float* ff_W1 = (const float*)d_in[14];
    const float* ff_b1 = (const float*)d_in[15];
    const float* ff_W2 = (const float*)d_in[16];
    const float* ff_b2 = (const float*)d_in[17];
    const float* ln1_g = (const float*)d_in[18];
    const float* ln1_b = (const float*)d_in[19];
    const float* ln2_g = (const float*)d_in[20];
    const float* ln2_b = (const float*)d_in[21];
    const float* ln3_g = (const float*)d_in[22];
    const float* ln3_b = (const float*)d_in[23];
    const float* head_b = (const float*)d_in[25];
    float* out = (float*)d_out;
    Scratch* s = get_s();
    static Ctx ctx;

    cudaFuncSetAttribute(gemm_tc<0, 0>, cudaFuncAttributeMaxDynamicSharedMemorySize, GEMM_SMEM);
    cudaFuncSetAttribute(gemm_tc<1, 1>, cudaFuncAttributeMaxDynamicSharedMemorySize, GEMM_SMEM);
    cudaFuncSetAttribute(gemm_tc<2, 0>, cudaFuncAttributeMaxDynamicSharedMemorySize, GEMM_SMEM);
    cudaFuncSetAttribute(gemm_tc<3, 1>, cudaFuncAttributeMaxDynamicSharedMemorySize, GEMM_SMEM);
    cudaFuncSetAttribute(gemm_tc<4, 1>, cudaFuncAttributeMaxDynamicSharedMemorySize, GEMM_SMEM);
    cudaFuncSetAttribute(softmax_combine_kernel, cudaFuncAttributeMaxDynamicSharedMemorySize,
                         2 * NTOK * (int)sizeof(float));

    const size_t WS = (size_t)DDIM * DDIM;
    const size_t nm = (size_t)NTOK * NTOK;
    const size_t nwords = nm / 32;
    const unsigned packGrid = (unsigned)(nwords / 32);
    dim3 ts2g(DDIM / 32, DDIM / 32, 2), tsb(32, 8);
#define WH(i) (s->w_h + (size_t)(i) * WS)
#define WL(i) (s->w_l + (size_t)(i) * WS)
    cudaStream_t sA = ctx.sA, sB = ctx.sB;

    cudaEventRecord(ctx.evStart, 0);
    cudaStreamWaitEvent(sA, ctx.evStart, 0);
    cudaStreamWaitEvent(sB, ctx.evStart, 0);

    pack_bits_kernel<<<packGrid, 256, 0, sA>>>(rmask, s->rbits, nwords);
    cudaEventRecord(ctx.evPackR, sA);
    prep_fused_kernel<<<NTOK + 512, 256>>>(x, drop_idx, s->dropx, s->dropx_h, s->dropx_l,
                                           W[0], W[1], WH(0), WL(0), WH(1), WL(1));
    cudaEventRecord(ctx.evPrep, 0);
    G_TCS(1, 1, NTOK, 1024, s->dropx_h, s->dropx_l, WH(0), WL(0), nullptr, s->QKr_h, s->QKr_l,
          nullptr, nullptr, DDIM, DDIM, DDIM, 1024, 0.f, 0);
    cudaStreamWaitEvent(0, ctx.evPackR, 0);
    G_TCS(2, 0, NTOK, NTOK, s->QKr_h, nullptr, s->QKr_h + DDIM, s->QKr_l + DDIM, s->Sr, nullptr, nullptr,
          nullptr, s->rbits, DDIM, 1024, 1024, NTOK, SCALE_C, 0);
    pack_bits_kernel<<<packGrid, 256, 0, sA>>>(fmask, s->fbits, nwords);
    tsplit2_kernel<<<ts2g, tsb, 0, sB>>>(W[2], W[3], WH(2), WL(2), WH(3), WL(3));
    cudaEventRecord(ctx.evW23, sB);
    cudaStreamWaitEvent(sA, ctx.evW23, 0);
    cudaStreamWaitEvent(sA, ctx.evPrep, 0);
    G_TCS(1, 1, NTOK, 1024, s->dropx_h, s->dropx_l, WH(2), WL(2), nullptr, s->QKf_h, s->QKf_l,
          nullptr, nullptr, DDIM, DDIM, DDIM, 1024, 0.f, sA);
    G_TCS(2, 0, NTOK, NTOK, s->QKf_h, nullptr, s->QKf_h + DDIM, s->QKf_l + DDIM, s->Sf, nullptr, nullptr,
          nullptr, s->fbits, DDIM, 1024, 1024, NTOK, SCALE_C, sA);
    cudaEventRecord(ctx.evSf, sA);
    tsplit2_kernel<<<dim3(DDIM / 32, DDIM / 32, 1), tsb, 0, sB>>>(W[4], W[4], WH(4), WL(4), WH(4), WL(4));
    cudaStreamWaitEvent(sB, ctx.evPrep, 0);
    G_TCS(1, 1, DDIM, NTOK, WH(4), WL(4), s->dropx_h, s->dropx_l, nullptr, s->Vt_h, s->Vt_l,
          nullptr, nullptr, DDIM, DDIM, DDIM, NTOK, 0.f, sB);
    cudaEventRecord(ctx.evVt, sB);
    cudaStreamWaitEvent(0, ctx.evSf, 0);
    cudaStreamWaitEvent(0, ctx.evVt, 0);
    softmax_combine_kernel<<<NTOK, 512, 2 * NTOK * sizeof(float)>>>(s->Sr, s->Sf, s->rbits, s->fbits, s->attn_h);
    G_TCS(0, 0, NTOK, DDIM, s->attn_h, nullptr, s->Vt_h, s->Vt_l, s->attnout, nullptr, nullptr,
          nullptr, nullptr, NTOK, NTOK, NTOK, DDIM, 0.f, 0);
    add_ln_kernel<<<NTOK, 256>>>(s->attnout, s->dropx, ln1_g, ln1_b, s->h1, s->h1_h, s->h1_l);
    tsplit_kernel<<<dim3(FDIM / 32, DDIM / 32), tsb, 0, sB>>>(ff_W1, s->w1_h, s->w1_l, DDIM, FDIM);
    tsplit_kernel<<<dim3(DDIM / 32, FDIM / 32), tsb, 0, sB>>>(ff_W2, s->w2_h, s->w2_l, FDIM, DDIM);
    cudaEventRecord(ctx.evFF, sB);
    cudaStreamWaitEvent(0, ctx.evFF, 0);
    G_TCS(3, 1, NTOK, FDIM, s->h1_h, s->h1_l, s->w1_h, s->w1_l, nullptr, s->ff_h, s->ff_l, ff_b1, nullptr,
          DDIM, DDIM, DDIM, FDIM, 0.f, 0);
    G_TCS(4, 1, NTOK, DDIM, s->ff_h, s->ff_l, s->w2_h, s->w2_l, s->attnout, nullptr, nullptr, ff_b2, nullptr,
          FDIM, FDIM, FDIM, DDIM, 0.f, 0);
    add_ln_kernel<<<NTOK, 256>>>(s->attnout, s->h1, ln2_g, ln2_b, s->h2, s->h2_h, s->h2_l);
    cudaEventRecord(ctx.evH2, 0);
    tsplit2_kernel<<<ts2g, tsb, 0, sB>>>(W[5], W[6], WH(5), WL(5), WH(6), WL(6));
    cudaEventRecord(ctx.evW56, sB);
    tsplit2_kernel<<<ts2g, tsb, 0, sB>>>(W[7], W[8], WH(7), WL(7), WH(8), WL(8));
    cudaEventRecord(ctx.evW78, sB);
    tsplit2_kernel<<<ts2g, tsb, 0, sB>>>(W[9], W[10], WH(9), WL(9), WH(10), WL(10));
    cudaEventRecord(ctx.evW910, sB);
    cudaStreamWaitEvent(0, ctx.evW56, 0);
    G_TCS(1, 1, NTOK, 1024, s->h2_h, s->h2_l, WH(5), WL(5), nullptr, s->QKr_h, s->QKr_l,
          nullptr, nullptr, DDIM, DDIM, DDIM, 1024, 0.f, 0);
    G_TCS(2, 0, NTOK, NTOK, s->QKr_h, nullptr, s->QKr_h + DDIM, s->QKr_l + DDIM, s->Sr, nullptr, nullptr,
          nullptr, s->rbits, DDIM, 1024, 1024, NTOK, SCALE_C, 0);
    cudaStreamWaitEvent(sA, ctx.evH2, 0);
    cudaStreamWaitEvent(sA, ctx.evW78, 0);
    G_TCS(1, 1, NTOK, 1024, s->h2_h, s->h2_l, WH(7), WL(7), nullptr, s->QKf_h, s->QKf_l,
          nullptr, nullptr, DDIM, DDIM, DDIM, 1024, 0.f, sA);
    G_TCS(2, 0, NTOK, NTOK, s->QKf_h, nullptr, s->QKf_h + DDIM, s->QKf_l + DDIM, s->Sf, nullptr, nullptr,
          nullptr, s->fbits, DDIM, 1024, 1024, NTOK, SCALE_C, sA);
    cudaEventRecord(ctx.evSfD, sA);
    cudaStreamWaitEvent(sB, ctx.evH2, 0);
    cudaStreamWaitEvent(sB, ctx.evW910, 0);
    G_TCS(1, 1, DDIM, NTOK, WH(9), WL(9), s->h2_h, s->h2_l, nullptr, s->Vt_h, s->Vt_l,
          nullptr, nullptr, DDIM, DDIM, DDIM, NTOK, 0.f, sB);
    cudaEventRecord(ctx.evVtD, sB);
    cudaStreamWaitEvent(0, ctx.evSfD, 0);
    cudaStreamWaitEvent(0, ctx.evVtD, 0);
    softmax_combine_kernel<<<NTOK, 512, 2 * NTOK * sizeof(float)>>>(s->Sr, s->Sf, s->rbits, s->fbits, s->attn_h);
    G_TCS(0, 0, NTOK, DDIM, s->attn_h, nullptr, s->Vt_h, s->Vt_l, s->attnout, nullptr, nullptr,
          nullptr, nullptr, NTOK, NTOK, NTOK, DDIM, 0.f, 0);
    add_ln_kernel<<<NTOK, 256>>>(s->attnout, s->h2, ln3_g, ln3_b, nullptr, s->rc_h, s->rc_l);
    G_TCS(4, 1, NTOK, DDIM, s->rc_h, s->rc_l, WH(10), WL(10), s->head, nullptr, nullptr,
          head_b, nullptr, DDIM, DDIM, DDIM, DDIM, 0.f, 0);
    gather_out_kernel<<<(NTOK * GDIM + 255) / 256, 256>>>(x, s->head, drop_idx, out);
}